// round 1
// baseline (speedup 1.0000x reference)
#include <cuda_runtime.h>
#include <math.h>

// Problem dims (fixed by setup_inputs)
#define GB 16
#define GN 8192
#define GC 64
#define GH 64
#define GW 64
#define NFREQ 64
#define DIN 194      // 64 z + 64 sin + 64 cos + 2 xy
#define HID 128
#define TP 16        // points per block
#define FEAT_LD 20   // smem row stride (floats); 20*4=80B -> 16B aligned rows, modest bank spread

typedef unsigned long long u64;

// 16 MB scratch: z_grid transposed to (B, H, W, C) so channel gathers coalesce.
__device__ float g_zt[GB * GH * GW * GC];

__global__ void __launch_bounds__(256) transpose_z_kernel(const float* __restrict__ z) {
    int i = blockIdx.x * 256 + threadIdx.x;      // over B*C*H*W, coalesced read
    int x = i & 63;
    int y = (i >> 6) & 63;
    int c = (i >> 12) & 63;
    int b = i >> 18;
    g_zt[(((((b << 6) + y) << 6) + x) << 6) + c] = z[i];
}

// ---- packed f32x2 helpers (Blackwell FFMA2 only reachable via PTX) ----
__device__ __forceinline__ u64 pack2(float lo, float hi) {
    u64 r; asm("mov.b64 %0,{%1,%2};" : "=l"(r) : "f"(lo), "f"(hi)); return r;
}
__device__ __forceinline__ void unpack2(u64 v, float& lo, float& hi) {
    asm("mov.b64 {%0,%1},%2;" : "=f"(lo), "=f"(hi) : "l"(v));
}
__device__ __forceinline__ void fma2(u64& d, u64 a, u64 b) {
    asm("fma.rn.f32x2 %0,%1,%2,%3;" : "=l"(d) : "l"(a), "l"(b), "l"(d));
}

// One dense layer: thread j owns output column j for all 16 points (8 f32x2 pairs).
// in_s rows are broadcast LDS.128; weight rows are coalesced LDG (L2-resident).
template<int K, bool DO_TANH>
__device__ __forceinline__ void dense_layer(const float* __restrict__ Wg,
                                            const float* __restrict__ bg,
                                            const float* in_s, float* out_s, int j) {
    u64 acc[8];
    #pragma unroll
    for (int i = 0; i < 8; i++) acc[i] = 0ull;

    #pragma unroll 4
    for (int k = 0; k < K; k++) {
        float w = Wg[k * HID + j];
        u64 wp = pack2(w, w);
        const ulonglong2* row = (const ulonglong2*)(in_s + k * FEAT_LD);
        ulonglong2 q0 = row[0], q1 = row[1], q2 = row[2], q3 = row[3];
        fma2(acc[0], q0.x, wp); fma2(acc[1], q0.y, wp);
        fma2(acc[2], q1.x, wp); fma2(acc[3], q1.y, wp);
        fma2(acc[4], q2.x, wp); fma2(acc[5], q2.y, wp);
        fma2(acc[6], q3.x, wp); fma2(acc[7], q3.y, wp);
    }

    float bj = bg[j];
    #pragma unroll
    for (int i = 0; i < 8; i++) {
        float lo, hi; unpack2(acc[i], lo, hi);
        lo += bj; hi += bj;
        if (DO_TANH) { lo = tanhf(lo); hi = tanhf(hi); }
        out_s[j * FEAT_LD + 2 * i]     = lo;
        out_s[j * FEAT_LD + 2 * i + 1] = hi;
    }
}

__global__ void __launch_bounds__(128) pinn_kernel(
    const float* __restrict__ coords,
    const float* __restrict__ fourierB,
    const float* __restrict__ W1,  const float* __restrict__ b1,
    const float* __restrict__ W2,  const float* __restrict__ b2,
    const float* __restrict__ W3,  const float* __restrict__ b3,
    const float* __restrict__ Wvel, const float* __restrict__ bvel,
    const float* __restrict__ Wfh,  const float* __restrict__ bfh,
    const float* __restrict__ Wph,  const float* __restrict__ bph,
    const float* __restrict__ Wmu,  const float* __restrict__ bmu,
    const float* __restrict__ Wstd, const float* __restrict__ bstd,
    float* __restrict__ out)
{
    __shared__ __align__(16) float sA[DIN * FEAT_LD];   // features / layer2 out
    __shared__ __align__(16) float sB[HID * FEAT_LD];   // layer1 / layer3 out
    __shared__ float sHW[HID * 8];                      // head weights [k][o]
    __shared__ float sHb[8];
    __shared__ float s_wa[TP], s_wb[TP], s_wc[TP], s_wd[TP], s_t[TP];
    __shared__ int   s_b00[TP], s_b01[TP], s_b10[TP], s_b11[TP];

    const int tid = threadIdx.x;
    const int m0  = blockIdx.x * TP;

    // ---- per-point bilinear setup (16 threads) ----
    if (tid < TP) {
        int m = m0 + tid;
        float cx = coords[m * 3 + 0];
        float cy = coords[m * 3 + 1];
        float ct = coords[m * 3 + 2];
        int b = m >> 13;                    // N = 8192
        float fx = (cx + 1.f) * 0.5f * (float)(GW - 1);
        float fy = (cy + 1.f) * 0.5f * (float)(GH - 1);
        float x0f = floorf(fx), y0f = floorf(fy);
        int x0 = min(max((int)x0f, 0), GW - 1);
        int x1 = max(min((int)x0f + 1, GW - 1), 0);
        int y0 = min(max((int)y0f, 0), GH - 1);
        int y1 = max(min((int)y0f + 1, GH - 1), 0);
        s_wa[tid] = (x0f + 1.f - fx) * (y0f + 1.f - fy);
        s_wb[tid] = (x0f + 1.f - fx) * (fy - y0f);
        s_wc[tid] = (fx - x0f) * (y0f + 1.f - fy);
        s_wd[tid] = (fx - x0f) * (fy - y0f);
        s_b00[tid] = (((((b << 6) + y0) << 6) + x0) << 6);
        s_b01[tid] = (((((b << 6) + y1) << 6) + x0) << 6);
        s_b10[tid] = (((((b << 6) + y0) << 6) + x1) << 6);
        s_b11[tid] = (((((b << 6) + y1) << 6) + x1) << 6);
        s_t[tid] = ct;
        sA[192 * FEAT_LD + tid] = cx;
        sA[193 * FEAT_LD + tid] = cy;
    }

    // ---- stage head weights: sHW[k][o], conflict-free reads later ----
    {
        int k = tid;
        sHW[k * 8 + 0] = Wvel[k * 2 + 0];
        sHW[k * 8 + 1] = Wvel[k * 2 + 1];
        sHW[k * 8 + 2] = Wfh[k * 2 + 0];
        sHW[k * 8 + 3] = Wfh[k * 2 + 1];
        sHW[k * 8 + 4] = Wph[k * 2 + 0];
        sHW[k * 8 + 5] = Wph[k * 2 + 1];
        sHW[k * 8 + 6] = Wmu[k];
        sHW[k * 8 + 7] = Wstd[k];
        if (tid < 8) {
            float hb;
            if      (tid < 2) hb = bvel[tid];
            else if (tid < 4) hb = bfh[tid - 2];
            else if (tid < 6) hb = bph[tid - 4];
            else if (tid == 6) hb = bmu[0];
            else               hb = bstd[0];
            sHb[tid] = hb;
        }
    }
    __syncthreads();

    // ---- features: bilinear z gather (coalesced over channels) + Fourier ----
    {
        int c  = tid & 63;
        int ph = tid >> 6;
        #pragma unroll
        for (int p8 = 0; p8 < 8; p8++) {
            int p = 2 * p8 + ph;
            float v = s_wa[p] * g_zt[s_b00[p] + c] + s_wb[p] * g_zt[s_b01[p] + c]
                    + s_wc[p] * g_zt[s_b10[p] + c] + s_wd[p] * g_zt[s_b11[p] + c];
            sA[c * FEAT_LD + p] = v;
        }
        float fb = fourierB[c] * 2.0943951023931953f;   // 2*pi/TEMPORAL_MAX
        #pragma unroll
        for (int p8 = 0; p8 < 8; p8++) {
            int p = 2 * p8 + ph;
            float sn, cs;
            sincosf(fb * s_t[p], &sn, &cs);
            sA[(64  + c) * FEAT_LD + p] = sn;
            sA[(128 + c) * FEAT_LD + p] = cs;
        }
    }
    __syncthreads();

    // ---- MLP trunk ----
    dense_layer<DIN, true>(W1, b1, sA, sB, tid);
    __syncthreads();
    dense_layer<HID, true>(W2, b2, sB, sA, tid);
    __syncthreads();
    dense_layer<HID, true>(W3, b3, sA, sB, tid);
    __syncthreads();

    // ---- heads: thread = (point p, output o) ----
    {
        int p = tid >> 3;
        int o = tid & 7;
        float a = 0.f;
        #pragma unroll 4
        for (int k = 0; k < HID; k++)
            a += sB[k * FEAT_LD + p] * sHW[k * 8 + o];
        a += sHb[o];
        if (o == 7) {
            // softplus(a) + MIN_STD, numerically stable
            a = fmaxf(a, 0.f) + log1pf(expf(-fabsf(a))) + 0.01f;
        }
        out[(m0 + p) * 8 + o] = a;
    }
}

extern "C" void kernel_launch(void* const* d_in, const int* in_sizes, int n_in,
                              void* d_out, int out_size) {
    const float* coords   = (const float*)d_in[0];
    const float* z_grid   = (const float*)d_in[1];
    const float* fourierB = (const float*)d_in[2];
    const float* W1   = (const float*)d_in[3];
    const float* b1   = (const float*)d_in[4];
    const float* W2   = (const float*)d_in[5];
    const float* b2   = (const float*)d_in[6];
    const float* W3   = (const float*)d_in[7];
    const float* b3   = (const float*)d_in[8];
    const float* Wvel = (const float*)d_in[9];
    const float* bvel = (const float*)d_in[10];
    const float* Wfh  = (const float*)d_in[11];
    const float* bfh  = (const float*)d_in[12];
    const float* Wph  = (const float*)d_in[13];
    const float* bph  = (const float*)d_in[14];
    const float* Wmu  = (const float*)d_in[15];
    const float* bmu  = (const float*)d_in[16];
    const float* Wstd = (const float*)d_in[17];
    const float* bstd = (const float*)d_in[18];
    float* out = (float*)d_out;

    transpose_z_kernel<<<(GB * GC * GH * GW) / 256, 256>>>(z_grid);
    pinn_kernel<<<(GB * GN) / TP, 128>>>(
        coords, fourierB, W1, b1, W2, b2, W3, b3,
        Wvel, bvel, Wfh, bfh, Wph, bph, Wmu, bmu, Wstd, bstd, out);
}

// round 4
// speedup vs baseline: 1.9079x; 1.9079x over previous
#include <cuda_runtime.h>
#include <cuda_bf16.h>
#include <math.h>
#include <stdint.h>

// ---------------- dims ----------------
#define NPTS 131072
#define PTS  128            // points per block (M tile)
#define TPB  256            // 8 warps
#define NBLK (NPTS/PTS)
#define HID  128
#define L1_KT 13            // K = 208 (194 real + bias row + pad)
#define L23_KT 8            // K = 128

// ---------------- strides / smem map (bytes) ----------------
#define SA_STRIDE 432       // A row stride: 216 bf16 (16B-aligned: 27*16)
#define SA_HALF   55296     // 128*432, lo buffer offset
#define SW_STRIDE 272       // W k-row stride: 136 bf16 (16B-aligned: 17*16)
#define SW_HALF   56576     // 208*272, lo buffer offset

#define SM_MBAR 0
#define SM_WH   64                       // head weights 128*8 f32
#define SM_HB   4160                     // 8 head biases
#define SM_B2   4224                     // b2 (128 f32)
#define SM_B3   4736                     // b3 (128 f32)
#define SM_A    5376                     // A hi | A lo (110592)
#define SM_W    (SM_A + 2*SA_HALF)       // 115968; W hi | W lo
#define SM_TOTAL (SM_W + 2*SW_HALF)      // 229120 (< 232448 max)

// W23 image: [128][136] bf16 = 34816 bytes per buffer
#define W23_SZ 34816

// ---------------- device scratch ----------------
__device__ float g_zt[16*64*64*64];                         // z transposed (B,H,W,C)
__device__ __align__(16) unsigned char g_W1img[2*SW_HALF];  // [208][136]bf16 hi | lo
__device__ __align__(16) unsigned char g_W23img[4*W23_SZ];  // L2 hi,lo | L3 hi,lo

// ---------------- helpers ----------------
__device__ __forceinline__ uint32_t smem_u32(const void* p) {
    uint32_t a;
    asm("{ .reg .u64 t; cvta.to.shared.u64 t, %1; cvt.u32.u64 %0, t; }" : "=r"(a) : "l"(p));
    return a;
}
#define MBAR_INIT(a,c)   asm volatile("mbarrier.init.shared.b64 [%0], %1;" :: "r"(a), "r"(c) : "memory")
#define MBAR_EXPECT(a,b) asm volatile("mbarrier.arrive.expect_tx.shared.b64 _, [%0], %1;" :: "r"(a), "r"(b) : "memory")
__device__ __forceinline__ void mbar_wait(uint32_t mbar, uint32_t parity) {
    uint32_t done;
    asm volatile("{ .reg .pred p; mbarrier.try_wait.parity.acquire.cta.shared::cta.b64 p, [%1], %2; selp.b32 %0,1,0,p; }"
                 : "=r"(done) : "r"(mbar), "r"(parity) : "memory");
    if (!done) {
        asm volatile("{ .reg .pred P1; WL%=: mbarrier.try_wait.parity.acquire.cta.shared::cta.b64 P1, [%0], %1, 0x989680;"
                     "@P1 bra.uni WD%=; bra.uni WL%=; WD%=: }" :: "r"(mbar), "r"(parity) : "memory");
    }
}
__device__ __forceinline__ void bulk_copy(uint32_t dst, const void* src, uint32_t bytes, uint32_t mbar) {
    asm volatile("cp.async.bulk.shared::cluster.global.mbarrier::complete_tx::bytes [%0], [%1], %2, [%3];"
                 :: "r"(dst), "l"(src), "r"(bytes), "r"(mbar) : "memory");
}
__device__ __forceinline__ void ldsm4(uint32_t* r, uint32_t a) {
    asm volatile("ldmatrix.sync.aligned.m8n8.x4.shared.b16 {%0,%1,%2,%3}, [%4];"
                 : "=r"(r[0]), "=r"(r[1]), "=r"(r[2]), "=r"(r[3]) : "r"(a));
}
__device__ __forceinline__ void ldsm4t(uint32_t* r, uint32_t a) {
    asm volatile("ldmatrix.sync.aligned.m8n8.x4.trans.shared.b16 {%0,%1,%2,%3}, [%4];"
                 : "=r"(r[0]), "=r"(r[1]), "=r"(r[2]), "=r"(r[3]) : "r"(a));
}
__device__ __forceinline__ void mma_bf16(float* d, const uint32_t* a, const uint32_t* b) {
    asm volatile("mma.sync.aligned.m16n8k16.row.col.f32.bf16.bf16.f32 "
                 "{%0,%1,%2,%3}, {%4,%5,%6,%7}, {%8,%9}, {%0,%1,%2,%3};"
                 : "+f"(d[0]), "+f"(d[1]), "+f"(d[2]), "+f"(d[3])
                 : "r"(a[0]), "r"(a[1]), "r"(a[2]), "r"(a[3]), "r"(b[0]), "r"(b[1]));
}
// pack (a,b) fp32 pair -> hi bf16x2 word + lo (residual) bf16x2 word
__device__ __forceinline__ void split2(float a, float b, uint32_t& hi, uint32_t& lo) {
    __nv_bfloat16 ah = __float2bfloat16(a), bh = __float2bfloat16(b);
    __nv_bfloat16 al = __float2bfloat16(a - __bfloat162float(ah));
    __nv_bfloat16 bl = __float2bfloat16(b - __bfloat162float(bh));
    hi = (uint32_t)__bfloat16_as_ushort(ah) | ((uint32_t)__bfloat16_as_ushort(bh) << 16);
    lo = (uint32_t)__bfloat16_as_ushort(al) | ((uint32_t)__bfloat16_as_ushort(bl) << 16);
}

// ---------------- prologue kernels ----------------
__global__ void __launch_bounds__(256) transpose_z_kernel(const float* __restrict__ z) {
    int i = blockIdx.x * 256 + threadIdx.x;
    int x = i & 63, y = (i >> 6) & 63, c = (i >> 12) & 63, b = i >> 18;
    g_zt[(((((b << 6) + y) << 6) + x) << 6) + c] = z[i];
}
__global__ void __launch_bounds__(256) prep_w1_kernel(const float* __restrict__ W1, const float* __restrict__ b1) {
    int i = blockIdx.x * 256 + threadIdx.x;
    if (i >= 208 * 136) return;
    int k = i / 136, n = i % 136;
    float v = 0.f;
    if (n < 128) { if (k < 194) v = W1[k * HID + n]; else if (k == 194) v = b1[n]; }
    __nv_bfloat16 hi = __float2bfloat16(v);
    __nv_bfloat16 lo = __float2bfloat16(v - __bfloat162float(hi));
    ((__nv_bfloat16*)g_W1img)[i] = hi;
    ((__nv_bfloat16*)(g_W1img + SW_HALF))[i] = lo;
}
__global__ void __launch_bounds__(256) prep_w23_kernel(const float* __restrict__ W2, const float* __restrict__ W3) {
    int i = blockIdx.x * 256 + threadIdx.x;
    if (i >= 2 * 128 * 136) return;
    int layer = i / 17408, r = i % 17408;
    int k = r / 136, n = r % 136;
    const float* W = layer ? W3 : W2;
    float v = (n < 128) ? W[k * HID + n] : 0.f;
    __nv_bfloat16 hi = __float2bfloat16(v);
    __nv_bfloat16 lo = __float2bfloat16(v - __bfloat162float(hi));
    unsigned char* base = g_W23img + layer * (2 * W23_SZ);
    ((__nv_bfloat16*)base)[r] = hi;
    ((__nv_bfloat16*)(base + W23_SZ))[r] = lo;
}

// ---------------- GEMM k-loop ----------------
template<int KT>
__device__ __forceinline__ void gemm_layer(float d[2][8][4], const uint32_t aAddr[2], uint32_t bAddr) {
    #pragma unroll 1
    for (int kt = 0; kt < KT; kt++) {
        uint32_t Ah[2][4], Al[2][4];
        #pragma unroll
        for (int mt = 0; mt < 2; mt++) {
            uint32_t a = aAddr[mt] + kt * 32;
            ldsm4(Ah[mt], a);
            ldsm4(Al[mt], a + SA_HALF);
        }
        #pragma unroll
        for (int np = 0; np < 4; np++) {
            uint32_t Bh[4], Bl[4];
            uint32_t ba = bAddr + kt * (16 * SW_STRIDE) + np * 32;
            ldsm4t(Bh, ba);
            ldsm4t(Bl, ba + SW_HALF);
            #pragma unroll
            for (int mt = 0; mt < 2; mt++) {
                mma_bf16(d[mt][2 * np],     Ah[mt], Bh);
                mma_bf16(d[mt][2 * np],     Al[mt], Bh);
                mma_bf16(d[mt][2 * np],     Ah[mt], Bl);
                mma_bf16(d[mt][2 * np + 1], Ah[mt], Bh + 2);
                mma_bf16(d[mt][2 * np + 1], Al[mt], Bh + 2);
                mma_bf16(d[mt][2 * np + 1], Ah[mt], Bl + 2);
            }
        }
    }
}

// ---------------- main kernel ----------------
__global__ void __launch_bounds__(TPB, 1) pinn_main(
    const float* __restrict__ coords, const float* __restrict__ fourierB,
    const float* __restrict__ b2g, const float* __restrict__ b3g,
    const float* __restrict__ Wvel, const float* __restrict__ bvel,
    const float* __restrict__ Wfh,  const float* __restrict__ bfh,
    const float* __restrict__ Wph,  const float* __restrict__ bph,
    const float* __restrict__ Wmu,  const float* __restrict__ bmu,
    const float* __restrict__ Wstd, const float* __restrict__ bstd,
    float* __restrict__ out)
{
    extern __shared__ __align__(16) unsigned char smem[];
    const uint32_t sb = smem_u32(smem);
    const int tid  = threadIdx.x;
    const int lane = tid & 31;
    const int warp = tid >> 5;
    const int mw = warp & 3;          // M warp (rows 32*mw..)
    const int nw = warp >> 2;         // N warp (cols 64*nw..)
    const int gid = lane >> 2, tig = lane & 3;

    float* sWh = (float*)(smem + SM_WH);
    float* sHb = (float*)(smem + SM_HB);
    float* sb2 = (float*)(smem + SM_B2);
    float* sb3 = (float*)(smem + SM_B3);

    if (tid == 0) MBAR_INIT(sb + SM_MBAR, 1);
    __syncthreads();
    if (tid == 0) {   // layer-1 weights: one contiguous copy (hi+lo)
        MBAR_EXPECT(sb + SM_MBAR, 2 * SW_HALF);
        bulk_copy(sb + SM_W, g_W1img, 2 * SW_HALF, sb + SM_MBAR);
    }

    // stage head weights / biases
    if (tid < 128) {
        int k = tid;
        sWh[k * 8 + 0] = Wvel[k * 2 + 0];
        sWh[k * 8 + 1] = Wvel[k * 2 + 1];
        sWh[k * 8 + 2] = Wfh[k * 2 + 0];
        sWh[k * 8 + 3] = Wfh[k * 2 + 1];
        sWh[k * 8 + 4] = Wph[k * 2 + 0];
        sWh[k * 8 + 5] = Wph[k * 2 + 1];
        sWh[k * 8 + 6] = Wmu[k];
        sWh[k * 8 + 7] = Wstd[k];
        sb2[k] = b2g[k];
        sb3[k] = b3g[k];
        if (tid < 8) {
            float hb;
            if      (tid < 2)  hb = bvel[tid];
            else if (tid < 4)  hb = bfh[tid - 2];
            else if (tid < 6)  hb = bph[tid - 4];
            else if (tid == 6) hb = bmu[0];
            else               hb = bstd[0];
            sHb[tid] = hb;
        }
    }

    // ---- feature build: 2 threads per point ----
    {
        int p = tid >> 1, role = tid & 1;
        int m = blockIdx.x * PTS + p;
        uint32_t rowOff = SM_A + (uint32_t)p * SA_STRIDE;
        if (role == 0) {
            float cx = coords[m * 3 + 0], cy = coords[m * 3 + 1];
            int b = m >> 13;
            float fx = (cx + 1.f) * 0.5f * 63.f;
            float fy = (cy + 1.f) * 0.5f * 63.f;
            float x0f = floorf(fx), y0f = floorf(fy);
            int x0 = min(max((int)x0f, 0), 63);
            int x1 = max(min((int)x0f + 1, 63), 0);
            int y0 = min(max((int)y0f, 0), 63);
            int y1 = max(min((int)y0f + 1, 63), 0);
            float wa = (x0f + 1.f - fx) * (y0f + 1.f - fy);
            float wb = (x0f + 1.f - fx) * (fy - y0f);
            float wc = (fx - x0f) * (y0f + 1.f - fy);
            float wd = (fx - x0f) * (fy - y0f);
            const float4* p00 = (const float4*)(g_zt + ((((b << 6) + y0) << 6) + x0) * 64);
            const float4* p01 = (const float4*)(g_zt + ((((b << 6) + y1) << 6) + x0) * 64);
            const float4* p10 = (const float4*)(g_zt + ((((b << 6) + y0) << 6) + x1) * 64);
            const float4* p11 = (const float4*)(g_zt + ((((b << 6) + y1) << 6) + x1) * 64);
            #pragma unroll
            for (int g = 0; g < 16; g++) {
                float4 A = p00[g], B = p01[g], C = p10[g], D = p11[g];
                float v0 = wa*A.x + wb*B.x + wc*C.x + wd*D.x;
                float v1 = wa*A.y + wb*B.y + wc*C.y + wd*D.y;
                float v2 = wa*A.z + wb*B.z + wc*C.z + wd*D.z;
                float v3 = wa*A.w + wb*B.w + wc*C.w + wd*D.w;
                uint32_t h0, l0, h1, l1;
                split2(v0, v1, h0, l0);
                split2(v2, v3, h1, l1);
                *(uint32_t*)(smem + rowOff + g * 8)               = h0;
                *(uint32_t*)(smem + rowOff + g * 8 + 4)           = h1;
                *(uint32_t*)(smem + rowOff + SA_HALF + g * 8)     = l0;
                *(uint32_t*)(smem + rowOff + SA_HALF + g * 8 + 4) = l1;
            }
            // tail: cols 192..207 -> (cx,cy), (1,0), zeros
            uint32_t h, l;
            split2(cx, cy, h, l);
            *(uint32_t*)(smem + rowOff + 384)           = h;
            *(uint32_t*)(smem + rowOff + SA_HALF + 384) = l;
            split2(1.f, 0.f, h, l);
            *(uint32_t*)(smem + rowOff + 388)           = h;
            *(uint32_t*)(smem + rowOff + SA_HALF + 388) = l;
            #pragma unroll
            for (int w = 0; w < 6; w++) {
                *(uint32_t*)(smem + rowOff + 392 + w * 4)           = 0;
                *(uint32_t*)(smem + rowOff + SA_HALF + 392 + w * 4) = 0;
            }
        } else {
            float ct = coords[m * 3 + 2];
            const float tscale = 2.0943951023931953f * ct;  // 2*pi/TEMPORAL_MAX * t
            #pragma unroll 8
            for (int f = 0; f < 32; f++) {
                float s0, c0, s1, c1;
                sincosf(fourierB[2 * f]     * tscale, &s0, &c0);
                sincosf(fourierB[2 * f + 1] * tscale, &s1, &c1);
                uint32_t hs, ls, hc, lc;
                split2(s0, s1, hs, ls);
                split2(c0, c1, hc, lc);
                *(uint32_t*)(smem + rowOff + 128 + f * 4)           = hs;  // cols 64..127
                *(uint32_t*)(smem + rowOff + SA_HALF + 128 + f * 4) = ls;
                *(uint32_t*)(smem + rowOff + 256 + f * 4)           = hc;  // cols 128..191
                *(uint32_t*)(smem + rowOff + SA_HALF + 256 + f * 4) = lc;
            }
        }
    }

    // lane-resolved ldmatrix base addresses
    uint32_t aAddr[2];
    {
        int half = lane >> 4;
        #pragma unroll
        for (int mt = 0; mt < 2; mt++) {
            int row = 32 * mw + 16 * mt + (lane & 15);
            aAddr[mt] = sb + SM_A + (uint32_t)row * SA_STRIDE + half * 16;
        }
    }
    uint32_t bAddr;
    {
        int krow = lane & 15, nhalf = (lane >> 4) * 8;
        bAddr = sb + SM_W + (uint32_t)krow * SW_STRIDE + (64 * nw + nhalf) * 2;
    }

    float d[2][8][4];

    // ================= layer 1 =================
    __syncthreads();               // A ready
    mbar_wait(sb + SM_MBAR, 0);    // W1 ready
    #pragma unroll
    for (int mt = 0; mt < 2; mt++)
        #pragma unroll
        for (int nt = 0; nt < 8; nt++)
            #pragma unroll
            for (int i = 0; i < 4; i++) d[mt][nt][i] = 0.f;
    gemm_layer<L1_KT>(d, aAddr, bAddr);
    __syncthreads();               // all warps done reading sA / sW
    if (tid == 0) {                // stage L2 weights
        MBAR_EXPECT(sb + SM_MBAR, 2 * W23_SZ);
        bulk_copy(sb + SM_W,           g_W23img,          W23_SZ, sb + SM_MBAR);
        bulk_copy(sb + SM_W + SW_HALF, g_W23img + W23_SZ, W23_SZ, sb + SM_MBAR);
    }
    // epilogue L1: tanh -> sA (bias folded into W1)
    #pragma unroll
    for (int mt = 0; mt < 2; mt++) {
        int r0 = 32 * mw + 16 * mt + gid;
        #pragma unroll
        for (int nt = 0; nt < 8; nt++) {
            int col = 64 * nw + 8 * nt + 2 * tig;
            uint32_t h, l;
            split2(tanhf(d[mt][nt][0]), tanhf(d[mt][nt][1]), h, l);
            *(uint32_t*)(smem + SM_A + r0 * SA_STRIDE + col * 2)           = h;
            *(uint32_t*)(smem + SM_A + SA_HALF + r0 * SA_STRIDE + col * 2) = l;
            split2(tanhf(d[mt][nt][2]), tanhf(d[mt][nt][3]), h, l);
            *(uint32_t*)(smem + SM_A + (r0 + 8) * SA_STRIDE + col * 2)           = h;
            *(uint32_t*)(smem + SM_A + SA_HALF + (r0 + 8) * SA_STRIDE + col * 2) = l;
        }
    }

    // ================= layer 2 =================
    __syncthreads();
    mbar_wait(sb + SM_MBAR, 1);
    #pragma unroll
    for (int mt = 0; mt < 2; mt++)
        #pragma unroll
        for (int nt = 0; nt < 8; nt++)
            #pragma unroll
            for (int i = 0; i < 4; i++) d[mt][nt][i] = 0.f;
    gemm_layer<L23_KT>(d, aAddr, bAddr);
    __syncthreads();
    if (tid == 0) {                // stage L3 weights
        MBAR_EXPECT(sb + SM_MBAR, 2 * W23_SZ);
        bulk_copy(sb + SM_W,           g_W23img + 2 * W23_SZ, W23_SZ, sb + SM_MBAR);
        bulk_copy(sb + SM_W + SW_HALF, g_W23img + 3 * W23_SZ, W23_SZ, sb + SM_MBAR);
    }
    // epilogue L2: +b2, tanh -> sA
    #pragma unroll
    for (int mt = 0; mt < 2; mt++) {
        int r0 = 32 * mw + 16 * mt + gid;
        #pragma unroll
        for (int nt = 0; nt < 8; nt++) {
            int col = 64 * nw + 8 * nt + 2 * tig;
            float bb0 = sb2[col], bb1 = sb2[col + 1];
            uint32_t h, l;
            split2(tanhf(d[mt][nt][0] + bb0), tanhf(d[mt][nt][1] + bb1), h, l);
            *(uint32_t*)(smem + SM_A + r0 * SA_STRIDE + col * 2)           = h;
            *(uint32_t*)(smem + SM_A + SA_HALF + r0 * SA_STRIDE + col * 2) = l;
            split2(tanhf(d[mt][nt][2] + bb0), tanhf(d[mt][nt][3] + bb1), h, l);
            *(uint32_t*)(smem + SM_A + (r0 + 8) * SA_STRIDE + col * 2)           = h;
            *(uint32_t*)(smem + SM_A + SA_HALF + (r0 + 8) * SA_STRIDE + col * 2) = l;
        }
    }

    // ================= layer 3 =================
    __syncthreads();
    mbar_wait(sb + SM_MBAR, 0);
    #pragma unroll
    for (int mt = 0; mt < 2; mt++)
        #pragma unroll
        for (int nt = 0; nt < 8; nt++)
            #pragma unroll
            for (int i = 0; i < 4; i++) d[mt][nt][i] = 0.f;
    gemm_layer<L23_KT>(d, aAddr, bAddr);
    __syncthreads();
    // epilogue L3: +b3, tanh -> fp32 feat (row stride 132 floats) in sA region
    {
        float* featF = (float*)(smem + SM_A);
        #pragma unroll
        for (int mt = 0; mt < 2; mt++) {
            int r0 = 32 * mw + 16 * mt + gid;
            #pragma unroll
            for (int nt = 0; nt < 8; nt++) {
                int col = 64 * nw + 8 * nt + 2 * tig;
                float bb0 = sb3[col], bb1 = sb3[col + 1];
                float2 v0 = make_float2(tanhf(d[mt][nt][0] + bb0), tanhf(d[mt][nt][1] + bb1));
                float2 v1 = make_float2(tanhf(d[mt][nt][2] + bb0), tanhf(d[mt][nt][3] + bb1));
                *(float2*)(featF + r0 * 132 + col)       = v0;
                *(float2*)(featF + (r0 + 8) * 132 + col) = v1;
            }
        }
    }
    __syncthreads();

    // ================= heads =================
    {
        const float* featF = (const float*)(smem + SM_A);
        int p = tid >> 1;
        int og = (tid & 1) * 4;
        const float4* wh4 = (const float4*)sWh;
        float a0 = 0.f, a1 = 0.f, a2 = 0.f, a3 = 0.f;
        #pragma unroll 4
        for (int k = 0; k < HID; k++) {
            float f = featF[p * 132 + k];
            float4 w = wh4[k * 2 + (tid & 1)];
            a0 += f * w.x; a1 += f * w.y; a2 += f * w.z; a3 += f * w.w;
        }
        a0 += sHb[og]; a1 += sHb[og + 1]; a2 += sHb[og + 2]; a3 += sHb[og + 3];
        if (og == 4) {  // output 7 = softplus(.) + MIN_STD
            a3 = fmaxf(a3, 0.f) + log1pf(expf(-fabsf(a3))) + 0.01f;
        }
        int m = blockIdx.x * PTS + p;
        *(float4*)(out + m * 8 + og) = make_float4(a0, a1, a2, a3);
    }
}

// ---------------- host launch ----------------
extern "C" void kernel_launch(void* const* d_in, const int* in_sizes, int n_in,
                              void* d_out, int out_size) {
    const float* coords   = (const float*)d_in[0];
    const float* z_grid   = (const float*)d_in[1];
    const float* fourierB = (const float*)d_in[2];
    const float* W1   = (const float*)d_in[3];
    const float* b1   = (const float*)d_in[4];
    const float* W2   = (const float*)d_in[5];
    const float* b2   = (const float*)d_in[6];
    const float* W3   = (const float*)d_in[7];
    const float* b3   = (const float*)d_in[8];
    const float* Wvel = (const float*)d_in[9];
    const float* bvel = (const float*)d_in[10];
    const float* Wfh  = (const float*)d_in[11];
    const float* bfh  = (const float*)d_in[12];
    const float* Wph  = (const float*)d_in[13];
    const float* bph  = (const float*)d_in[14];
    const float* Wmu  = (const float*)d_in[15];
    const float* bmu  = (const float*)d_in[16];
    const float* Wstd = (const float*)d_in[17];
    const float* bstd = (const float*)d_in[18];
    float* out = (float*)d_out;

    static bool attr_set = false;
    if (!attr_set) {
        cudaFuncSetAttribute(pinn_main, cudaFuncAttributeMaxDynamicSharedMemorySize, SM_TOTAL);
        attr_set = true;
    }

    transpose_z_kernel<<<(16 * 64 * 64 * 64) / 256, 256>>>(z_grid);
    prep_w1_kernel<<<(208 * 136 + 255) / 256, 256>>>(W1, b1);
    prep_w23_kernel<<<(2 * 128 * 136 + 255) / 256, 256>>>(W2, W3);
    pinn_main<<<NBLK, TPB, SM_TOTAL>>>(
        coords, fourierB, b2, b3,
        Wvel, bvel, Wfh, bfh, Wph, bph, Wmu, bmu, Wstd, bstd, out);
}

// round 5
// speedup vs baseline: 2.1621x; 1.1333x over previous
#include <cuda_runtime.h>
#include <cuda_bf16.h>
#include <math.h>
#include <stdint.h>

// ---------------- dims ----------------
#define NPTS 131072
#define PTS  128            // points per block (M tile)
#define TPB  256            // 8 warps
#define NBLK (NPTS/PTS)
#define HID  128
#define L1_KT 13            // K = 208 (194 real + bias row + pad)
#define L23_KT 8            // K = 128

// ---------------- A smem layout (bytes) ----------------
#define SA_STRIDE 432       // A row stride: 216 bf16 (16B-aligned, 2-way ldsm conflicts max)
#define SA_HALF   55296     // 128*432, lo buffer offset
#define SM_B2 0             // b2: 128 f32
#define SM_B3 512           // b3: 128 f32
#define SM_A  1024
#define SM_TOTAL (SM_A + 2*SA_HALF)   // 111616 -> 2 blocks/SM

// weight fragment array (uint4 units): L1 13*16*32=6656 | L2 4096 | L3 4096
#define WF_L1 0
#define WF_L2 6656
#define WF_L3 10752
#define WF_TOTAL 14848

// ---------------- device scratch ----------------
__device__ float g_zt[16*64*64*64];          // z transposed (B,H,W,C)
__device__ uint4 g_wfrag[WF_TOTAL];          // MMA b-fragments {b0h,b1h,b0l,b1l}
__device__ float g_wh[HID*8];                // head weights [k][o]
__device__ float g_hb[8];                    // head biases

// ---------------- helpers ----------------
__device__ __forceinline__ uint32_t smem_u32(const void* p) {
    uint32_t a;
    asm("{ .reg .u64 t; cvta.to.shared.u64 t, %1; cvt.u32.u64 %0, t; }" : "=r"(a) : "l"(p));
    return a;
}
__device__ __forceinline__ void ldsm4(uint32_t* r, uint32_t a) {
    asm volatile("ldmatrix.sync.aligned.m8n8.x4.shared.b16 {%0,%1,%2,%3}, [%4];"
                 : "=r"(r[0]), "=r"(r[1]), "=r"(r[2]), "=r"(r[3]) : "r"(a));
}
__device__ __forceinline__ void mma_bf16(float* d, const uint32_t* a, uint32_t b0, uint32_t b1) {
    asm volatile("mma.sync.aligned.m16n8k16.row.col.f32.bf16.bf16.f32 "
                 "{%0,%1,%2,%3}, {%4,%5,%6,%7}, {%8,%9}, {%0,%1,%2,%3};"
                 : "+f"(d[0]), "+f"(d[1]), "+f"(d[2]), "+f"(d[3])
                 : "r"(a[0]), "r"(a[1]), "r"(a[2]), "r"(a[3]), "r"(b0), "r"(b1));
}
// pack (a,b) fp32 pair -> hi bf16x2 word + lo (residual) bf16x2 word (low halfword = first elem)
__device__ __forceinline__ void split2(float a, float b, uint32_t& hi, uint32_t& lo) {
    __nv_bfloat16 ah = __float2bfloat16(a), bh = __float2bfloat16(b);
    __nv_bfloat16 al = __float2bfloat16(a - __bfloat162float(ah));
    __nv_bfloat16 bl = __float2bfloat16(b - __bfloat162float(bh));
    hi = (uint32_t)__bfloat16_as_ushort(ah) | ((uint32_t)__bfloat16_as_ushort(bh) << 16);
    lo = (uint32_t)__bfloat16_as_ushort(al) | ((uint32_t)__bfloat16_as_ushort(bl) << 16);
}

// ---------------- prologue kernels ----------------
__global__ void __launch_bounds__(256) transpose_z_kernel(const float* __restrict__ z) {
    int i = blockIdx.x * 256 + threadIdx.x;
    int x = i & 63, y = (i >> 6) & 63, c = (i >> 12) & 63, b = i >> 18;
    g_zt[(((((b << 6) + y) << 6) + x) << 6) + c] = z[i];
}

// Pre-pack weights into MMA col-major b-fragment layout.
// For m16n8k16: lane l, n-tile nt, k-tile kt:  n = nt*8 + l/4,  k0 = kt*16 + (l%4)*2
//   b0 = {W[k0][n], W[k0+1][n]},  b1 = {W[k0+8][n], W[k0+9][n]}
__global__ void __launch_bounds__(256) prep_wfrag_kernel(
    const float* __restrict__ W1, const float* __restrict__ b1,
    const float* __restrict__ W2, const float* __restrict__ W3)
{
    int i = blockIdx.x * 256 + threadIdx.x;
    if (i >= WF_TOTAL) return;
    int layer, rem;
    const float* W;
    if (i < WF_L2)      { layer = 1; rem = i;          W = W1; }
    else if (i < WF_L3) { layer = 2; rem = i - WF_L2;  W = W2; }
    else                { layer = 3; rem = i - WF_L3;  W = W3; }
    int lane = rem & 31, nt = (rem >> 5) & 15, kt = rem >> 9;
    int n  = nt * 8 + (lane >> 2);
    int k0 = kt * 16 + (lane & 3) * 2;
    float v[4];
    #pragma unroll
    for (int j = 0; j < 4; j++) {
        int k = k0 + (j >> 1) * 8 + (j & 1);
        float val;
        if (layer == 1) {
            if (k < 194)       val = W[k * HID + n];
            else if (k == 194) val = b1[n];
            else               val = 0.f;
        } else {
            val = W[k * HID + n];
        }
        v[j] = val;
    }
    uint4 o;
    split2(v[0], v[1], o.x, o.z);
    split2(v[2], v[3], o.y, o.w);
    g_wfrag[i] = o;
}

__global__ void __launch_bounds__(128) prep_heads_kernel(
    const float* __restrict__ Wvel, const float* __restrict__ bvel,
    const float* __restrict__ Wfh,  const float* __restrict__ bfh,
    const float* __restrict__ Wph,  const float* __restrict__ bph,
    const float* __restrict__ Wmu,  const float* __restrict__ bmu,
    const float* __restrict__ Wstd, const float* __restrict__ bstd)
{
    int k = threadIdx.x;
    g_wh[k * 8 + 0] = Wvel[k * 2 + 0];
    g_wh[k * 8 + 1] = Wvel[k * 2 + 1];
    g_wh[k * 8 + 2] = Wfh[k * 2 + 0];
    g_wh[k * 8 + 3] = Wfh[k * 2 + 1];
    g_wh[k * 8 + 4] = Wph[k * 2 + 0];
    g_wh[k * 8 + 5] = Wph[k * 2 + 1];
    g_wh[k * 8 + 6] = Wmu[k];
    g_wh[k * 8 + 7] = Wstd[k];
    if (k < 8) {
        float hb;
        if      (k < 2)  hb = bvel[k];
        else if (k < 4)  hb = bfh[k - 2];
        else if (k < 6)  hb = bph[k - 4];
        else if (k == 6) hb = bmu[0];
        else             hb = bstd[0];
        g_hb[k] = hb;
    }
}

// ---------------- GEMM k-loop: A from smem (ldmatrix), B frags from global ----------------
template<int KT>
__device__ __forceinline__ void gemm_layer(float d[2][8][4], const uint32_t aAddr[2],
                                           const uint4* __restrict__ wf) {
    #pragma unroll 1
    for (int kt = 0; kt < KT; kt++) {
        uint32_t Ah[2][4], Al[2][4];
        #pragma unroll
        for (int mt = 0; mt < 2; mt++) {
            uint32_t a = aAddr[mt] + kt * 32;
            ldsm4(Ah[mt], a);
            ldsm4(Al[mt], a + SA_HALF);
        }
        const uint4* p = wf + kt * 512;          // 16 nt * 32 lanes per kt
        #pragma unroll
        for (int nt = 0; nt < 8; nt++) {
            uint4 B = __ldg(p + nt * 32);        // coalesced 512B per warp
            #pragma unroll
            for (int mt = 0; mt < 2; mt++) {
                mma_bf16(d[mt][nt], Ah[mt], B.x, B.y);   // AhBh
                mma_bf16(d[mt][nt], Al[mt], B.x, B.y);   // AlBh
                mma_bf16(d[mt][nt], Ah[mt], B.z, B.w);   // AhBl
            }
        }
    }
}

// ---------------- main kernel ----------------
__global__ void __launch_bounds__(TPB, 2) pinn_main(
    const float* __restrict__ coords, const float* __restrict__ fourierB,
    const float* __restrict__ b2g, const float* __restrict__ b3g,
    float* __restrict__ out)
{
    extern __shared__ __align__(16) unsigned char smem[];
    const uint32_t sb = smem_u32(smem);
    const int tid  = threadIdx.x;
    const int lane = tid & 31;
    const int warp = tid >> 5;
    const int mw = warp & 3;          // M warp (rows 32*mw..)
    const int nw = warp >> 2;         // N warp (cols 64*nw..)
    const int gid = lane >> 2, tig = lane & 3;

    float* sb2 = (float*)(smem + SM_B2);
    float* sb3 = (float*)(smem + SM_B3);
    if (tid < 128)      sb2[tid] = b2g[tid];
    else                sb3[tid - 128] = b3g[tid - 128];

    // ---- feature build: 2 threads per point ----
    {
        int p = tid >> 1, role = tid & 1;
        int m = blockIdx.x * PTS + p;
        uint32_t rowOff = SM_A + (uint32_t)p * SA_STRIDE;
        if (role == 0) {
            float cx = coords[m * 3 + 0], cy = coords[m * 3 + 1];
            int b = m >> 13;
            float fx = (cx + 1.f) * 0.5f * 63.f;
            float fy = (cy + 1.f) * 0.5f * 63.f;
            float x0f = floorf(fx), y0f = floorf(fy);
            int x0 = min(max((int)x0f, 0), 63);
            int x1 = max(min((int)x0f + 1, 63), 0);
            int y0 = min(max((int)y0f, 0), 63);
            int y1 = max(min((int)y0f + 1, 63), 0);
            float wa = (x0f + 1.f - fx) * (y0f + 1.f - fy);
            float wb = (x0f + 1.f - fx) * (fy - y0f);
            float wc = (fx - x0f) * (y0f + 1.f - fy);
            float wd = (fx - x0f) * (fy - y0f);
            const float4* p00 = (const float4*)(g_zt + ((((b << 6) + y0) << 6) + x0) * 64);
            const float4* p01 = (const float4*)(g_zt + ((((b << 6) + y1) << 6) + x0) * 64);
            const float4* p10 = (const float4*)(g_zt + ((((b << 6) + y0) << 6) + x1) * 64);
            const float4* p11 = (const float4*)(g_zt + ((((b << 6) + y1) << 6) + x1) * 64);
            #pragma unroll
            for (int g = 0; g < 16; g++) {
                float4 A = p00[g], B = p01[g], C = p10[g], D = p11[g];
                float v0 = wa*A.x + wb*B.x + wc*C.x + wd*D.x;
                float v1 = wa*A.y + wb*B.y + wc*C.y + wd*D.y;
                float v2 = wa*A.z + wb*B.z + wc*C.z + wd*D.z;
                float v3 = wa*A.w + wb*B.w + wc*C.w + wd*D.w;
                uint32_t h0, l0, h1, l1;
                split2(v0, v1, h0, l0);
                split2(v2, v3, h1, l1);
                *(uint32_t*)(smem + rowOff + g * 8)               = h0;
                *(uint32_t*)(smem + rowOff + g * 8 + 4)           = h1;
                *(uint32_t*)(smem + rowOff + SA_HALF + g * 8)     = l0;
                *(uint32_t*)(smem + rowOff + SA_HALF + g * 8 + 4) = l1;
            }
            // tail: cols 192..207 -> (cx,cy), (1,0), zeros
            uint32_t h, l;
            split2(cx, cy, h, l);
            *(uint32_t*)(smem + rowOff + 384)           = h;
            *(uint32_t*)(smem + rowOff + SA_HALF + 384) = l;
            split2(1.f, 0.f, h, l);
            *(uint32_t*)(smem + rowOff + 388)           = h;
            *(uint32_t*)(smem + rowOff + SA_HALF + 388) = l;
            #pragma unroll
            for (int w = 0; w < 6; w++) {
                *(uint32_t*)(smem + rowOff + 392 + w * 4)           = 0;
                *(uint32_t*)(smem + rowOff + SA_HALF + 392 + w * 4) = 0;
            }
        } else {
            float ct = coords[m * 3 + 2];
            const float tscale = 2.0943951023931953f * ct;  // 2*pi/TEMPORAL_MAX * t
            #pragma unroll 8
            for (int f = 0; f < 32; f++) {
                float s0, c0, s1, c1;
                sincosf(fourierB[2 * f]     * tscale, &s0, &c0);
                sincosf(fourierB[2 * f + 1] * tscale, &s1, &c1);
                uint32_t hs, ls, hc, lc;
                split2(s0, s1, hs, ls);
                split2(c0, c1, hc, lc);
                *(uint32_t*)(smem + rowOff + 128 + f * 4)           = hs;  // cols 64..127
                *(uint32_t*)(smem + rowOff + SA_HALF + 128 + f * 4) = ls;
                *(uint32_t*)(smem + rowOff + 256 + f * 4)           = hc;  // cols 128..191
                *(uint32_t*)(smem + rowOff + SA_HALF + 256 + f * 4) = lc;
            }
        }
    }

    // lane-resolved ldmatrix A addresses
    uint32_t aAddr[2];
    {
        int half = lane >> 4;
        #pragma unroll
        for (int mt = 0; mt < 2; mt++) {
            int row = 32 * mw + 16 * mt + (lane & 15);
            aAddr[mt] = sb + SM_A + (uint32_t)row * SA_STRIDE + half * 16;
        }
    }
    // per-warp fragment base: nw selects cols 64*nw..; lane-resolved
    const uint4* wfBase = g_wfrag + (uint32_t)(nw * 8) * 32 + lane;

    float d[2][8][4];

    // ================= layer 1 =================
    __syncthreads();               // A ready
    #pragma unroll
    for (int mt = 0; mt < 2; mt++)
        #pragma unroll
        for (int nt = 0; nt < 8; nt++)
            #pragma unroll
            for (int i = 0; i < 4; i++) d[mt][nt][i] = 0.f;
    gemm_layer<L1_KT>(d, aAddr, wfBase + WF_L1);
    __syncthreads();               // all warps done reading sA
    // epilogue L1: tanh -> sA (bias folded into W1)
    #pragma unroll
    for (int mt = 0; mt < 2; mt++) {
        int r0 = 32 * mw + 16 * mt + gid;
        #pragma unroll
        for (int nt = 0; nt < 8; nt++) {
            int col = 64 * nw + 8 * nt + 2 * tig;
            uint32_t h, l;
            split2(tanhf(d[mt][nt][0]), tanhf(d[mt][nt][1]), h, l);
            *(uint32_t*)(smem + SM_A + r0 * SA_STRIDE + col * 2)           = h;
            *(uint32_t*)(smem + SM_A + SA_HALF + r0 * SA_STRIDE + col * 2) = l;
            split2(tanhf(d[mt][nt][2]), tanhf(d[mt][nt][3]), h, l);
            *(uint32_t*)(smem + SM_A + (r0 + 8) * SA_STRIDE + col * 2)           = h;
            *(uint32_t*)(smem + SM_A + SA_HALF + (r0 + 8) * SA_STRIDE + col * 2) = l;
        }
    }

    // ================= layer 2 =================
    __syncthreads();
    #pragma unroll
    for (int mt = 0; mt < 2; mt++)
        #pragma unroll
        for (int nt = 0; nt < 8; nt++)
            #pragma unroll
            for (int i = 0; i < 4; i++) d[mt][nt][i] = 0.f;
    gemm_layer<L23_KT>(d, aAddr, wfBase + WF_L2);
    __syncthreads();
    // epilogue L2: +b2, tanh -> sA
    #pragma unroll
    for (int mt = 0; mt < 2; mt++) {
        int r0 = 32 * mw + 16 * mt + gid;
        #pragma unroll
        for (int nt = 0; nt < 8; nt++) {
            int col = 64 * nw + 8 * nt + 2 * tig;
            float bb0 = sb2[col], bb1 = sb2[col + 1];
            uint32_t h, l;
            split2(tanhf(d[mt][nt][0] + bb0), tanhf(d[mt][nt][1] + bb1), h, l);
            *(uint32_t*)(smem + SM_A + r0 * SA_STRIDE + col * 2)           = h;
            *(uint32_t*)(smem + SM_A + SA_HALF + r0 * SA_STRIDE + col * 2) = l;
            split2(tanhf(d[mt][nt][2] + bb0), tanhf(d[mt][nt][3] + bb1), h, l);
            *(uint32_t*)(smem + SM_A + (r0 + 8) * SA_STRIDE + col * 2)           = h;
            *(uint32_t*)(smem + SM_A + SA_HALF + (r0 + 8) * SA_STRIDE + col * 2) = l;
        }
    }

    // ================= layer 3 =================
    __syncthreads();
    #pragma unroll
    for (int mt = 0; mt < 2; mt++)
        #pragma unroll
        for (int nt = 0; nt < 8; nt++)
            #pragma unroll
            for (int i = 0; i < 4; i++) d[mt][nt][i] = 0.f;
    gemm_layer<L23_KT>(d, aAddr, wfBase + WF_L3);
    __syncthreads();
    // epilogue L3: +b3, tanh -> fp32 feat (row stride 132 floats) in sA region
    {
        float* featF = (float*)(smem + SM_A);
        #pragma unroll
        for (int mt = 0; mt < 2; mt++) {
            int r0 = 32 * mw + 16 * mt + gid;
            #pragma unroll
            for (int nt = 0; nt < 8; nt++) {
                int col = 64 * nw + 8 * nt + 2 * tig;
                float bb0 = sb3[col], bb1 = sb3[col + 1];
                float2 v0 = make_float2(tanhf(d[mt][nt][0] + bb0), tanhf(d[mt][nt][1] + bb1));
                float2 v1 = make_float2(tanhf(d[mt][nt][2] + bb0), tanhf(d[mt][nt][3] + bb1));
                *(float2*)(featF + r0 * 132 + col)       = v0;
                *(float2*)(featF + (r0 + 8) * 132 + col) = v1;
            }
        }
    }
    __syncthreads();

    // ================= heads =================
    {
        const float* featF = (const float*)(smem + SM_A);
        int p = tid >> 1;
        int og = (tid & 1) * 4;
        const float4* wh4 = (const float4*)g_wh;
        float a0 = 0.f, a1 = 0.f, a2 = 0.f, a3 = 0.f;
        #pragma unroll 4
        for (int k = 0; k < HID; k++) {
            float f = featF[p * 132 + k];
            float4 w = __ldg(wh4 + k * 2 + (tid & 1));
            a0 += f * w.x; a1 += f * w.y; a2 += f * w.z; a3 += f * w.w;
        }
        a0 += g_hb[og]; a1 += g_hb[og + 1]; a2 += g_hb[og + 2]; a3 += g_hb[og + 3];
        if (og == 4) {  // output 7 = softplus(.) + MIN_STD
            a3 = fmaxf(a3, 0.f) + log1pf(expf(-fabsf(a3))) + 0.01f;
        }
        int m = blockIdx.x * PTS + p;
        *(float4*)(out + m * 8 + og) = make_float4(a0, a1, a2, a3);
    }
}

// ---------------- host launch ----------------
extern "C" void kernel_launch(void* const* d_in, const int* in_sizes, int n_in,
                              void* d_out, int out_size) {
    const float* coords   = (const float*)d_in[0];
    const float* z_grid   = (const float*)d_in[1];
    const float* fourierB = (const float*)d_in[2];
    const float* W1   = (const float*)d_in[3];
    const float* b1   = (const float*)d_in[4];
    const float* W2   = (const float*)d_in[5];
    const float* b2   = (const float*)d_in[6];
    const float* W3   = (const float*)d_in[7];
    const float* b3   = (const float*)d_in[8];
    const float* Wvel = (const float*)d_in[9];
    const float* bvel = (const float*)d_in[10];
    const float* Wfh  = (const float*)d_in[11];
    const float* bfh  = (const float*)d_in[12];
    const float* Wph  = (const float*)d_in[13];
    const float* bph  = (const float*)d_in[14];
    const float* Wmu  = (const float*)d_in[15];
    const float* bmu  = (const float*)d_in[16];
    const float* Wstd = (const float*)d_in[17];
    const float* bstd = (const float*)d_in[18];
    float* out = (float*)d_out;

    static bool attr_set = false;
    if (!attr_set) {
        cudaFuncSetAttribute(pinn_main, cudaFuncAttributeMaxDynamicSharedMemorySize, SM_TOTAL);
        attr_set = true;
    }

    transpose_z_kernel<<<(16 * 64 * 64 * 64) / 256, 256>>>(z_grid);
    prep_wfrag_kernel<<<(WF_TOTAL + 255) / 256, 256>>>(W1, b1, W2, W3);
    prep_heads_kernel<<<1, 128>>>(Wvel, bvel, Wfh, bfh, Wph, bph, Wmu, bmu, Wstd, bstd);
    pinn_main<<<NBLK, TPB, SM_TOTAL>>>(coords, fourierB, b2, b3, out);
}

// round 6
// speedup vs baseline: 2.1723x; 1.0047x over previous
#include <cuda_runtime.h>
#include <cuda_bf16.h>
#include <math.h>
#include <stdint.h>

// ---------------- dims ----------------
#define NPTS 131072
#define PTS  64             // points per block
#define TPB  128            // 4 warps, each owns 16 points x full N=128
#define NBLK (NPTS/PTS)     // 2048
#define HID  128
#define L1_KT 13            // K = 208 (194 real + bias row + pad)
#define L23_KT 8            // K = 128

// ---------------- A smem layout (bytes) ----------------
#define SA_STRIDE 432       // feature row stride: 216 bf16 (16B-aligned)
#define SA_HALF   27648     // 64*432, lo buffer offset
#define SM_B2 0             // b2: 128 f32
#define SM_B3 512           // b3: 128 f32
#define SM_A  1024
#define SM_TOTAL (SM_A + 2*SA_HALF)   // 56320 -> 3 blocks/SM (regs-capped)

// weight fragment array (uint4 units): [layer][kt][nt 0..15][lane]
#define WF_L1 0
#define WF_L2 6656          // 13*512
#define WF_L3 10752
#define WF_TOTAL 14848

// ---------------- device scratch ----------------
__device__ float g_zt[16*64*64*64];          // z transposed (B,H,W,C)
__device__ uint4 g_wfrag[WF_TOTAL];          // MMA b-fragments {b0h,b1h,b0l,b1l}
__device__ float g_wh[HID*8];                // head weights [k][o]
__device__ float g_hb[8];                    // head biases

// ---------------- helpers ----------------
__device__ __forceinline__ uint32_t smem_u32(const void* p) {
    uint32_t a;
    asm("{ .reg .u64 t; cvta.to.shared.u64 t, %1; cvt.u32.u64 %0, t; }" : "=r"(a) : "l"(p));
    return a;
}
__device__ __forceinline__ void ldsm4(uint32_t* r, uint32_t a) {
    asm volatile("ldmatrix.sync.aligned.m8n8.x4.shared.b16 {%0,%1,%2,%3}, [%4];"
                 : "=r"(r[0]), "=r"(r[1]), "=r"(r[2]), "=r"(r[3]) : "r"(a));
}
__device__ __forceinline__ void mma_bf16(float* d, const uint32_t* a, uint32_t b0, uint32_t b1) {
    asm volatile("mma.sync.aligned.m16n8k16.row.col.f32.bf16.bf16.f32 "
                 "{%0,%1,%2,%3}, {%4,%5,%6,%7}, {%8,%9}, {%0,%1,%2,%3};"
                 : "+f"(d[0]), "+f"(d[1]), "+f"(d[2]), "+f"(d[3])
                 : "r"(a[0]), "r"(a[1]), "r"(a[2]), "r"(a[3]), "r"(b0), "r"(b1));
}
// fast tanh: 1 - 2/(exp(2x)+1). MUFU ex2 + rcp.approx; branch-free; ~1e-6 err
__device__ __forceinline__ float ftanh(float x) {
    float e = __expf(2.f * x);
    float r;
    asm("rcp.approx.f32 %0, %1;" : "=f"(r) : "f"(e + 1.f));
    return fmaf(-2.f, r, 1.f);
}
// pack (a,b) fp32 pair -> hi bf16x2 word + lo (residual) bf16x2 word
__device__ __forceinline__ void split2(float a, float b, uint32_t& hi, uint32_t& lo) {
    __nv_bfloat16 ah = __float2bfloat16(a), bh = __float2bfloat16(b);
    __nv_bfloat16 al = __float2bfloat16(a - __bfloat162float(ah));
    __nv_bfloat16 bl = __float2bfloat16(b - __bfloat162float(bh));
    hi = (uint32_t)__bfloat16_as_ushort(ah) | ((uint32_t)__bfloat16_as_ushort(bh) << 16);
    lo = (uint32_t)__bfloat16_as_ushort(al) | ((uint32_t)__bfloat16_as_ushort(bl) << 16);
}

// ---------------- prologue kernels ----------------
__global__ void __launch_bounds__(256) transpose_z_kernel(const float* __restrict__ z) {
    int i = blockIdx.x * 256 + threadIdx.x;
    int x = i & 63, y = (i >> 6) & 63, c = (i >> 12) & 63, b = i >> 18;
    g_zt[(((((b << 6) + y) << 6) + x) << 6) + c] = z[i];
}

// Pre-pack weights into MMA col-major b-fragment layout.
// lane l, n-tile nt, k-tile kt:  n = nt*8 + l/4,  k0 = kt*16 + (l%4)*2
//   b0 = {W[k0][n], W[k0+1][n]},  b1 = {W[k0+8][n], W[k0+9][n]}
__global__ void __launch_bounds__(256) prep_wfrag_kernel(
    const float* __restrict__ W1, const float* __restrict__ b1,
    const float* __restrict__ W2, const float* __restrict__ W3)
{
    int i = blockIdx.x * 256 + threadIdx.x;
    if (i >= WF_TOTAL) return;
    int layer, rem;
    const float* W;
    if (i < WF_L2)      { layer = 1; rem = i;          W = W1; }
    else if (i < WF_L3) { layer = 2; rem = i - WF_L2;  W = W2; }
    else                { layer = 3; rem = i - WF_L3;  W = W3; }
    int lane = rem & 31, nt = (rem >> 5) & 15, kt = rem >> 9;
    int n  = nt * 8 + (lane >> 2);
    int k0 = kt * 16 + (lane & 3) * 2;
    float v[4];
    #pragma unroll
    for (int j = 0; j < 4; j++) {
        int k = k0 + (j >> 1) * 8 + (j & 1);
        float val;
        if (layer == 1) {
            if (k < 194)       val = W[k * HID + n];
            else if (k == 194) val = b1[n];
            else               val = 0.f;
        } else {
            val = W[k * HID + n];
        }
        v[j] = val;
    }
    uint4 o;
    split2(v[0], v[1], o.x, o.z);
    split2(v[2], v[3], o.y, o.w);
    g_wfrag[i] = o;
}

__global__ void __launch_bounds__(128) prep_heads_kernel(
    const float* __restrict__ Wvel, const float* __restrict__ bvel,
    const float* __restrict__ Wfh,  const float* __restrict__ bfh,
    const float* __restrict__ Wph,  const float* __restrict__ bph,
    const float* __restrict__ Wmu,  const float* __restrict__ bmu,
    const float* __restrict__ Wstd, const float* __restrict__ bstd)
{
    int k = threadIdx.x;
    g_wh[k * 8 + 0] = Wvel[k * 2 + 0];
    g_wh[k * 8 + 1] = Wvel[k * 2 + 1];
    g_wh[k * 8 + 2] = Wfh[k * 2 + 0];
    g_wh[k * 8 + 3] = Wfh[k * 2 + 1];
    g_wh[k * 8 + 4] = Wph[k * 2 + 0];
    g_wh[k * 8 + 5] = Wph[k * 2 + 1];
    g_wh[k * 8 + 6] = Wmu[k];
    g_wh[k * 8 + 7] = Wstd[k];
    if (k < 8) {
        float hb;
        if      (k < 2)  hb = bvel[k];
        else if (k < 4)  hb = bfh[k - 2];
        else if (k < 6)  hb = bph[k - 4];
        else if (k == 6) hb = bmu[0];
        else             hb = bstd[0];
        g_hb[k] = hb;
    }
}

// ---------------- main kernel ----------------
__global__ void __launch_bounds__(TPB, 3) pinn_main(
    const float* __restrict__ coords, const float* __restrict__ fourierB,
    const float* __restrict__ b2g, const float* __restrict__ b3g,
    float* __restrict__ out)
{
    extern __shared__ __align__(16) unsigned char smem[];
    const uint32_t sb = smem_u32(smem);
    const int tid  = threadIdx.x;
    const int lane = tid & 31;
    const int warp = tid >> 5;        // 0..3, owns rows warp*16..warp*16+15

    float* sb2 = (float*)(smem + SM_B2);
    float* sb3 = (float*)(smem + SM_B3);
    sb2[tid] = b2g[tid];
    sb3[tid] = b3g[tid];

    // ---- feature build: 2 threads per point (64 points) ----
    {
        int p = tid >> 1, role = tid & 1;
        int m = blockIdx.x * PTS + p;
        uint32_t rowOff = SM_A + (uint32_t)p * SA_STRIDE;
        if (role == 0) {
            float cx = coords[m * 3 + 0], cy = coords[m * 3 + 1];
            int b = m >> 13;
            float fx = (cx + 1.f) * 0.5f * 63.f;
            float fy = (cy + 1.f) * 0.5f * 63.f;
            float x0f = floorf(fx), y0f = floorf(fy);
            int x0 = min(max((int)x0f, 0), 63);
            int x1 = max(min((int)x0f + 1, 63), 0);
            int y0 = min(max((int)y0f, 0), 63);
            int y1 = max(min((int)y0f + 1, 63), 0);
            float wa = (x0f + 1.f - fx) * (y0f + 1.f - fy);
            float wb = (x0f + 1.f - fx) * (fy - y0f);
            float wc = (fx - x0f) * (y0f + 1.f - fy);
            float wd = (fx - x0f) * (fy - y0f);
            const float4* p00 = (const float4*)(g_zt + ((((b << 6) + y0) << 6) + x0) * 64);
            const float4* p01 = (const float4*)(g_zt + ((((b << 6) + y1) << 6) + x0) * 64);
            const float4* p10 = (const float4*)(g_zt + ((((b << 6) + y0) << 6) + x1) * 64);
            const float4* p11 = (const float4*)(g_zt + ((((b << 6) + y1) << 6) + x1) * 64);
            #pragma unroll
            for (int g = 0; g < 16; g++) {
                float4 A = p00[g], B = p01[g], C = p10[g], D = p11[g];
                float v0 = wa*A.x + wb*B.x + wc*C.x + wd*D.x;
                float v1 = wa*A.y + wb*B.y + wc*C.y + wd*D.y;
                float v2 = wa*A.z + wb*B.z + wc*C.z + wd*D.z;
                float v3 = wa*A.w + wb*B.w + wc*C.w + wd*D.w;
                uint32_t h0, l0, h1, l1;
                split2(v0, v1, h0, l0);
                split2(v2, v3, h1, l1);
                *(uint32_t*)(smem + rowOff + g * 8)               = h0;
                *(uint32_t*)(smem + rowOff + g * 8 + 4)           = h1;
                *(uint32_t*)(smem + rowOff + SA_HALF + g * 8)     = l0;
                *(uint32_t*)(smem + rowOff + SA_HALF + g * 8 + 4) = l1;
            }
            // tail: cols 192..207 -> (cx,cy), (1,0), zeros
            uint32_t h, l;
            split2(cx, cy, h, l);
            *(uint32_t*)(smem + rowOff + 384)           = h;
            *(uint32_t*)(smem + rowOff + SA_HALF + 384) = l;
            split2(1.f, 0.f, h, l);
            *(uint32_t*)(smem + rowOff + 388)           = h;
            *(uint32_t*)(smem + rowOff + SA_HALF + 388) = l;
            #pragma unroll
            for (int w = 0; w < 6; w++) {
                *(uint32_t*)(smem + rowOff + 392 + w * 4)           = 0;
                *(uint32_t*)(smem + rowOff + SA_HALF + 392 + w * 4) = 0;
            }
        } else {
            float ct = coords[m * 3 + 2];
            const float tscale = 2.0943951023931953f * ct;  // 2*pi/TEMPORAL_MAX * t
            #pragma unroll 8
            for (int f = 0; f < 32; f++) {
                float s0, c0, s1, c1;
                sincosf(fourierB[2 * f]     * tscale, &s0, &c0);
                sincosf(fourierB[2 * f + 1] * tscale, &s1, &c1);
                uint32_t hs, ls, hc, lc;
                split2(s0, s1, hs, ls);
                split2(c0, c1, hc, lc);
                *(uint32_t*)(smem + rowOff + 128 + f * 4)           = hs;  // cols 64..127
                *(uint32_t*)(smem + rowOff + SA_HALF + 128 + f * 4) = ls;
                *(uint32_t*)(smem + rowOff + 256 + f * 4)           = hc;  // cols 128..191
                *(uint32_t*)(smem + rowOff + SA_HALF + 256 + f * 4) = lc;
            }
        }
    }
    __syncthreads();   // features + biases ready; after this, warps are independent

    // ldmatrix A address for this warp's 16 rows
    const uint32_t aAddr = sb + SM_A + (uint32_t)(warp * 16 + (lane & 15)) * SA_STRIDE + (lane >> 4) * 16;

    float d[16][4];

    // ================= layer 1 (A from smem) =================
    #pragma unroll
    for (int nt = 0; nt < 16; nt++)
        #pragma unroll
        for (int i = 0; i < 4; i++) d[nt][i] = 0.f;
    {
        const uint4* wf = g_wfrag + WF_L1 + lane;
        #pragma unroll 1
        for (int kt = 0; kt < L1_KT; kt++) {
            uint32_t Ah[4], Al[4];
            ldsm4(Ah, aAddr + kt * 32);
            ldsm4(Al, aAddr + kt * 32 + SA_HALF);
            const uint4* p = wf + kt * 512;
            #pragma unroll
            for (int nt = 0; nt < 16; nt++) {
                uint4 B = __ldg(p + nt * 32);
                mma_bf16(d[nt], Ah, B.x, B.y);
                mma_bf16(d[nt], Al, B.x, B.y);
                mma_bf16(d[nt], Ah, B.z, B.w);
            }
        }
    }

    // epilogue 1 -> A2 in registers (bias folded into W1); D-frag == A-frag layout
    uint32_t A2h[8][4], A2l[8][4];
    #pragma unroll
    for (int kt = 0; kt < 8; kt++)
        #pragma unroll
        for (int j = 0; j < 4; j++) {
            int srcnt = 2 * kt + (j >> 1);
            int c = (j & 1) * 2;
            split2(ftanh(d[srcnt][c]), ftanh(d[srcnt][c + 1]), A2h[kt][j], A2l[kt][j]);
        }

    // ================= layer 2 (A in registers) =================
    #pragma unroll
    for (int nt = 0; nt < 16; nt++)
        #pragma unroll
        for (int i = 0; i < 4; i++) d[nt][i] = 0.f;
    {
        const uint4* wf = g_wfrag + WF_L2 + lane;
        #pragma unroll
        for (int kt = 0; kt < L23_KT; kt++) {
            const uint4* p = wf + kt * 512;
            #pragma unroll
            for (int nt = 0; nt < 16; nt++) {
                uint4 B = __ldg(p + nt * 32);
                mma_bf16(d[nt], A2h[kt], B.x, B.y);
                mma_bf16(d[nt], A2l[kt], B.x, B.y);
                mma_bf16(d[nt], A2h[kt], B.z, B.w);
            }
        }
    }

    // epilogue 2: +b2, tanh -> A3 (reuse A2 arrays)
    #pragma unroll
    for (int kt = 0; kt < 8; kt++)
        #pragma unroll
        for (int j = 0; j < 4; j++) {
            int srcnt = 2 * kt + (j >> 1);
            int c = (j & 1) * 2;
            int col = 8 * srcnt + (lane & 3) * 2;
            float2 bb = *(float2*)(sb2 + col);
            split2(ftanh(d[srcnt][c] + bb.x), ftanh(d[srcnt][c + 1] + bb.y),
                   A2h[kt][j], A2l[kt][j]);
        }

    // ================= layer 3 (A in registers) =================
    #pragma unroll
    for (int nt = 0; nt < 16; nt++)
        #pragma unroll
        for (int i = 0; i < 4; i++) d[nt][i] = 0.f;
    {
        const uint4* wf = g_wfrag + WF_L3 + lane;
        #pragma unroll
        for (int kt = 0; kt < L23_KT; kt++) {
            const uint4* p = wf + kt * 512;
            #pragma unroll
            for (int nt = 0; nt < 16; nt++) {
                uint4 B = __ldg(p + nt * 32);
                mma_bf16(d[nt], A2h[kt], B.x, B.y);
                mma_bf16(d[nt], A2l[kt], B.x, B.y);
                mma_bf16(d[nt], A2h[kt], B.z, B.w);
            }
        }
    }

    // epilogue 3: +b3, tanh -> fp32 feat in smem (stride 132 floats)
    {
        float* featF = (float*)(smem + SM_A);
        int row0 = warp * 16 + (lane >> 2);
        #pragma unroll
        for (int nt = 0; nt < 16; nt++) {
            int col = 8 * nt + (lane & 3) * 2;
            float2 bb = *(float2*)(sb3 + col);
            *(float2*)(featF + row0 * 132 + col) =
                make_float2(ftanh(d[nt][0] + bb.x), ftanh(d[nt][1] + bb.y));
            *(float2*)(featF + (row0 + 8) * 132 + col) =
                make_float2(ftanh(d[nt][2] + bb.x), ftanh(d[nt][3] + bb.y));
        }
    }
    __syncthreads();

    // ================= heads =================
    {
        const float* featF = (const float*)(smem + SM_A);
        int p = tid >> 1;
        int og = (tid & 1) * 4;
        const float4* wh4 = (const float4*)g_wh;
        float a0 = 0.f, a1 = 0.f, a2 = 0.f, a3 = 0.f;
        #pragma unroll 4
        for (int k = 0; k < HID; k++) {
            float f = featF[p * 132 + k];
            float4 w = __ldg(wh4 + k * 2 + (tid & 1));
            a0 += f * w.x; a1 += f * w.y; a2 += f * w.z; a3 += f * w.w;
        }
        a0 += g_hb[og]; a1 += g_hb[og + 1]; a2 += g_hb[og + 2]; a3 += g_hb[og + 3];
        if (og == 4) {  // output 7 = softplus(.) + MIN_STD
            a3 = fmaxf(a3, 0.f) + log1pf(expf(-fabsf(a3))) + 0.01f;
        }
        int m = blockIdx.x * PTS + p;
        *(float4*)(out + m * 8 + og) = make_float4(a0, a1, a2, a3);
    }
}

// ---------------- host launch ----------------
extern "C" void kernel_launch(void* const* d_in, const int* in_sizes, int n_in,
                              void* d_out, int out_size) {
    const float* coords   = (const float*)d_in[0];
    const float* z_grid   = (const float*)d_in[1];
    const float* fourierB = (const float*)d_in[2];
    const float* W1   = (const float*)d_in[3];
    const float* b1   = (const float*)d_in[4];
    const float* W2   = (const float*)d_in[5];
    const float* b2   = (const float*)d_in[6];
    const float* W3   = (const float*)d_in[7];
    const float* b3   = (const float*)d_in[8];
    const float* Wvel = (const float*)d_in[9];
    const float* bvel = (const float*)d_in[10];
    const float* Wfh  = (const float*)d_in[11];
    const float* bfh  = (const float*)d_in[12];
    const float* Wph  = (const float*)d_in[13];
    const float* bph  = (const float*)d_in[14];
    const float* Wmu  = (const float*)d_in[15];
    const float* bmu  = (const float*)d_in[16];
    const float* Wstd = (const float*)d_in[17];
    const float* bstd = (const float*)d_in[18];
    float* out = (float*)d_out;

    static bool attr_set = false;
    if (!attr_set) {
        cudaFuncSetAttribute(pinn_main, cudaFuncAttributeMaxDynamicSharedMemorySize, SM_TOTAL);
        attr_set = true;
    }

    transpose_z_kernel<<<(16 * 64 * 64 * 64) / 256, 256>>>(z_grid);
    prep_wfrag_kernel<<<(WF_TOTAL + 255) / 256, 256>>>(W1, b1, W2, W3);
    prep_heads_kernel<<<1, 128>>>(Wvel, bvel, Wfh, bfh, Wph, bph, Wmu, bmu, Wstd, bstd);
    pinn_main<<<NBLK, TPB, SM_TOTAL>>>(coords, fourierB, b2, b3, out);
}